// round 6
// baseline (speedup 1.0000x reference)
#include <cuda_runtime.h>
#include <cstdint>
#include <math.h>

#define T_SEQ 1024
#define E_DIM 256
#define NHEAD 8
#define HDIM 32
#define HALF 16
#define BNUM 8          // B*N = 2*4
#define BH (BNUM*NHEAD) // 64
#define ROWS_TOT (BNUM*T_SEQ)   // 8192

typedef unsigned long long ull;

// Scratch (static device arrays; no allocation allowed)
__device__ float g_q[BNUM * T_SEQ * E_DIM];     // [bh][t][d]
__device__ float g_k[BNUM * T_SEQ * E_DIM];
__device__ float g_v[BNUM * T_SEQ * E_DIM];
__device__ float g_attT[E_DIM * ROWS_TOT];      // TRANSPOSED: [e][bn*T + t]
__device__ float g_po[2 * BH * T_SEQ * HDIM];   // split-K partial o (unnormalized)
__device__ float g_pm[2 * BH * T_SEQ];          // split-K partial max (log2 domain)
__device__ float g_pl[2 * BH * T_SEQ];          // split-K partial sum
__device__ float g_cos[T_SEQ * HALF];
__device__ float g_sin[T_SEQ * HALF];

// ---------------------------------------------------------------------------
// f32x2 packed-math helpers
// ---------------------------------------------------------------------------
__device__ __forceinline__ ull pack2(float lo, float hi) {
    ull r;
    asm("mov.b64 %0, {%1, %2};" : "=l"(r) : "f"(lo), "f"(hi));
    return r;
}
__device__ __forceinline__ void unpack2(ull v, float& lo, float& hi) {
    asm("mov.b64 {%0, %1}, %2;" : "=f"(lo), "=f"(hi) : "l"(v));
}
__device__ __forceinline__ ull fma2(ull a, ull b, ull c) {
    ull d;
    asm("fma.rn.f32x2 %0, %1, %2, %3;" : "=l"(d) : "l"(a), "l"(b), "l"(c));
    return d;
}
__device__ __forceinline__ ull mul2(ull a, ull b) {
    ull d;
    asm("mul.rn.f32x2 %0, %1, %2;" : "=l"(d) : "l"(a), "l"(b));
    return d;
}

// cp.async helpers (16B)
__device__ __forceinline__ void cp_async16(uint32_t saddr, const void* gptr) {
    asm volatile("cp.async.cg.shared.global [%0], [%1], 16;" :: "r"(saddr), "l"(gptr));
}
__device__ __forceinline__ void cp_commit() {
    asm volatile("cp.async.commit_group;");
}
template <int N>
__device__ __forceinline__ void cp_wait() {
    asm volatile("cp.async.wait_group %0;" :: "n"(N));
}
__device__ __forceinline__ uint32_t smem_u32(const void* p) {
    uint32_t a;
    asm("{ .reg .u64 t; cvta.to.shared.u64 t, %1; cvt.u32.u64 %0, t; }" : "=r"(a) : "l"(p));
    return a;
}

// ---------------------------------------------------------------------------
// RoPE table. fp64 only for the 16 inv_freq pows + range reduction.
// ---------------------------------------------------------------------------
__global__ __launch_bounds__(256) void rope_table_kernel() {
    __shared__ double s_inv[HALF];
    if (threadIdx.x < HALF) {
        s_inv[threadIdx.x] = pow(10000.0, -(double)threadIdx.x / 16.0);
    }
    __syncthreads();
    int i = blockIdx.x * blockDim.x + threadIdx.x;
    int t = i >> 4;
    int f = i & 15;
    float angf = (float)t * (float)s_inv[f];       // fp32, matches reference
    double ad = (double)angf;
    double k  = rint(ad * 0.15915494309189535);
    double r  = ad - k * 6.283185307179586;
    float rf  = (float)r;
    g_cos[i] = cosf(rf);
    g_sin[i] = sinf(rf);
}

// ---------------------------------------------------------------------------
// Fused QKV GEMM + RoPE. gridDim.y in {0,1,2} selects the q / k / v output
// group (256 cols each). 32 rows per block, 256 threads: one output column
// per thread, 32-row accumulator in 16 packed f32x2 regs.
// ---------------------------------------------------------------------------
#define QKV_ROWS 32
#define XPAD 36   // row stride (floats): 16B-aligned (144B), 4-way store conflicts max
__global__ __launch_bounds__(256) void qkv_rope_kernel(
    const float* __restrict__ inp,   // [B, T, 4, E]
    const float* __restrict__ w,     // [E, 3E]
    const float* __restrict__ bias)  // [3E]
{
    __shared__ __align__(16) float sxT[E_DIM][XPAD];   // 36KB transposed x
    __shared__ float scos[QKV_ROWS][HALF];
    __shared__ float ssin[QKV_ROWS][HALF];

    const int tid = threadIdx.x;
    const int grp = blockIdx.y;              // 0=q, 1=k, 2=v
    const int col = grp * E_DIM + tid;       // column in [0, 768)
    const int r0 = blockIdx.x * QKV_ROWS;
    const int bn = r0 / T_SEQ;
    const int t0 = r0 % T_SEQ;
    const int b  = bn >> 2;
    const int n  = bn & 3;

    #pragma unroll
    for (int rr = 0; rr < QKV_ROWS; rr++) {
        sxT[tid][rr] = inp[(((size_t)(b * T_SEQ + t0 + rr) * 4) + n) * E_DIM + tid];
    }
    // stage rope table rows (512 floats, 2 per thread)
    {
        const int i0 = tid, i1 = tid + 256;
        scos[i0 >> 4][i0 & 15] = g_cos[(t0 + (i0 >> 4)) * HALF + (i0 & 15)];
        scos[i1 >> 4][i1 & 15] = g_cos[(t0 + (i1 >> 4)) * HALF + (i1 & 15)];
        ssin[i0 >> 4][i0 & 15] = g_sin[(t0 + (i0 >> 4)) * HALF + (i0 & 15)];
        ssin[i1 >> 4][i1 & 15] = g_sin[(t0 + (i1 >> 4)) * HALF + (i1 & 15)];
    }
    __syncthreads();

    const float bb = bias[col];
    ull acc[16];
    #pragma unroll
    for (int p = 0; p < 16; p++) acc[p] = pack2(bb, bb);

    #pragma unroll 1
    for (int e0 = 0; e0 < E_DIM; e0 += 8) {
        float wr[8];
        #pragma unroll
        for (int j = 0; j < 8; j++) wr[j] = w[(e0 + j) * 768 + col];
        #pragma unroll
        for (int j = 0; j < 8; j++) {
            const ull w2 = pack2(wr[j], wr[j]);
            const ulonglong2* xp = (const ulonglong2*)&sxT[e0 + j][0];
            #pragma unroll
            for (int q = 0; q < 8; q++) {
                const ulonglong2 xx = xp[q];
                acc[2 * q]     = fma2(xx.x, w2, acc[2 * q]);
                acc[2 * q + 1] = fma2(xx.y, w2, acc[2 * q + 1]);
            }
        }
    }

    const int h  = tid >> 5;
    const int dd = tid & 31;
    const size_t rowbase = ((size_t)(bn * NHEAD + h) * T_SEQ + t0) * HDIM + dd;

    if (grp == 2) {
        // v: no rope
        #pragma unroll
        for (int p = 0; p < 16; p++) {
            float f0, f1;
            unpack2(acc[p], f0, f1);
            g_v[rowbase + (size_t)(2 * p) * HDIM]       = f0;
            g_v[rowbase + (size_t)(2 * p + 1) * HDIM]   = f1;
        }
    } else {
        float* dst = (grp == 0) ? g_q : g_k;
        const int f = dd & 15;
        const float sgn = (dd < HALF) ? -1.0f : 1.0f;
        #pragma unroll
        for (int p = 0; p < 16; p++) {
            float f0, f1;
            unpack2(acc[p], f0, f1);
            const float p0 = __shfl_xor_sync(0xffffffffu, f0, 16);
            const float p1 = __shfl_xor_sync(0xffffffffu, f1, 16);
            const int ra = 2 * p, rb = 2 * p + 1;
            dst[rowbase + (size_t)ra * HDIM] = f0 * scos[ra][f] + sgn * p0 * ssin[ra][f];
            dst[rowbase + (size_t)rb * HDIM] = f1 * scos[rb][f] + sgn * p1 * ssin[rb][f];
        }
    }
}

// ---------------------------------------------------------------------------
// Flash attention stage 1 (split-K x2), cp.async double-buffered K/V tiles,
// exp2-domain softmax.
// ---------------------------------------------------------------------------
#define TQ 128
#define TK 32
#define KSPLIT 512
__global__ __launch_bounds__(TQ) void attn_kernel() {
    const int qt  = 7 - blockIdx.x;         // heavy tiles first
    const int bh  = blockIdx.y;
    const int sp  = blockIdx.z;
    const int tid = threadIdx.x;
    const int qrow = qt * TQ + tid;
    const size_t pidx = ((size_t)sp * BH + bh) * T_SEQ + qrow;

    const int kbeg = sp * KSPLIT;
    const int kend = min((sp + 1) * KSPLIT, (qt + 1) * TQ);

    if (kbeg >= kend) {                     // empty split (sp=1, qt<4)
        g_pm[pidx] = -1e30f;
        g_pl[pidx] = 0.0f;
        ull* op = (ull*)(g_po + pidx * HDIM);
        #pragma unroll
        for (int i = 0; i < 16; i++) op[i] = 0ull;
        return;
    }

    __shared__ __align__(16) float Ks[2][TK][HDIM];
    __shared__ __align__(16) float Vs[2][TK][HDIM];

    const float scale = 0.17677669529663687f * 1.4426950408889634f; // /sqrt(32)*log2(e)
    const ull scale2 = pack2(scale, scale);

    ull qd[16];
    {
        const ull* qp = (const ull*)(g_q + ((size_t)bh * T_SEQ + qrow) * HDIM);
        #pragma unroll
        for (int i = 0; i < 16; i++) qd[i] = mul2(qp[i], scale2);
    }

    ull od[16];
    #pragma unroll
    for (int i = 0; i < 16; i++) od[i] = 0ull;
    float m = -1e30f, l = 0.0f;

    const int ntiles = (kend - kbeg) / TK;

    {
        const float* ksrc = g_k + ((size_t)bh * T_SEQ + kbeg) * HDIM;
        const float* vsrc = g_v + ((size_t)bh * T_SEQ + kbeg) * HDIM;
        const uint32_t kdst = smem_u32(&Ks[0][0][0]);
        const uint32_t vdst = smem_u32(&Vs[0][0][0]);
        #pragma unroll
        for (int i = 0; i < 2; i++) {
            const int off = (tid + i * TQ) * 4;
            cp_async16(kdst + off * 4, ksrc + off);
            cp_async16(vdst + off * 4, vsrc + off);
        }
        cp_commit();
    }

    for (int kt = 0; kt < ntiles; kt++) {
        const int k0 = kbeg + kt * TK;
        if (kt + 1 < ntiles) {
            const int nb = (kt + 1) & 1;
            const float* ksrc = g_k + ((size_t)bh * T_SEQ + k0 + TK) * HDIM;
            const float* vsrc = g_v + ((size_t)bh * T_SEQ + k0 + TK) * HDIM;
            const uint32_t kdst = smem_u32(&Ks[nb][0][0]);
            const uint32_t vdst = smem_u32(&Vs[nb][0][0]);
            #pragma unroll
            for (int i = 0; i < 2; i++) {
                const int off = (tid + i * TQ) * 4;
                cp_async16(kdst + off * 4, ksrc + off);
                cp_async16(vdst + off * 4, vsrc + off);
            }
            cp_commit();
            cp_wait<1>();
        } else {
            cp_wait<0>();
        }
        __syncthreads();
        const int cb = kt & 1;

        float s[TK];
        #pragma unroll
        for (int j = 0; j < TK; j++) {
            ull acc = 0ull;
            const ulonglong2* kp = (const ulonglong2*)&Ks[cb][j][0];
            #pragma unroll
            for (int i = 0; i < 8; i++) {
                const ulonglong2 kk = kp[i];
                acc = fma2(qd[2 * i], kk.x, acc);
                acc = fma2(qd[2 * i + 1], kk.y, acc);
            }
            float lo, hi;
            unpack2(acc, lo, hi);
            s[j] = (k0 + j <= qrow) ? (lo + hi) : -1e30f;
        }

        float mt = m;
        #pragma unroll
        for (int j = 0; j < TK; j++) mt = fmaxf(mt, s[j]);
        const float alpha = exp2f(m - mt);
        m = mt;
        l *= alpha;
        const ull alpha2 = pack2(alpha, alpha);
        #pragma unroll
        for (int i = 0; i < 16; i++) od[i] = mul2(od[i], alpha2);

        #pragma unroll
        for (int j = 0; j < TK; j++) {
            const float p = exp2f(s[j] - m);
            l += p;
            const ull p2 = pack2(p, p);
            const ulonglong2* vp = (const ulonglong2*)&Vs[cb][j][0];
            #pragma unroll
            for (int i = 0; i < 8; i++) {
                const ulonglong2 vvv = vp[i];
                od[2 * i]     = fma2(p2, vvv.x, od[2 * i]);
                od[2 * i + 1] = fma2(p2, vvv.y, od[2 * i + 1]);
            }
        }
        __syncthreads();
    }

    g_pm[pidx] = m;
    g_pl[pidx] = l;
    ull* op = (ull*)(g_po + pidx * HDIM);
    #pragma unroll
    for (int i = 0; i < 16; i++) op[i] = od[i];
}

// ---------------------------------------------------------------------------
// Stage 2: merge split-K partials; write TRANSPOSED g_attT[e][row].
// ---------------------------------------------------------------------------
__global__ __launch_bounds__(TQ) void combine_kernel() {
    __shared__ float Os[HDIM][TQ + 1];
    __shared__ float sw0[TQ], sw1[TQ], sinv[TQ];

    const int qt  = blockIdx.x;
    const int bh  = blockIdx.y;
    const int tid = threadIdx.x;
    const int qrow = qt * TQ + tid;
    const size_t p0 = ((size_t)bh) * T_SEQ + qrow;
    const size_t p1 = ((size_t)BH + bh) * T_SEQ + qrow;

    const float m0 = g_pm[p0], m1 = g_pm[p1];
    const float l0 = g_pl[p0], l1 = g_pl[p1];
    const float M  = fmaxf(m0, m1);
    const float w0 = exp2f(m0 - M);
    const float w1 = exp2f(m1 - M);
    sw0[tid]  = w0;
    sw1[tid]  = w1;
    sinv[tid] = 1.0f / (w0 * l0 + w1 * l1);
    __syncthreads();

    const float* o0 = g_po + (((size_t)bh) * T_SEQ + qt * TQ) * HDIM;
    const float* o1 = g_po + (((size_t)BH + bh) * T_SEQ + qt * TQ) * HDIM;
    #pragma unroll
    for (int i = 0; i < 32; i++) {
        const int idx = i * TQ + tid;
        const int d = idx & 31;
        const int r = idx >> 5;
        Os[d][r] = (sw0[r] * o0[idx] + sw1[r] * o1[idx]) * sinv[r];
    }
    __syncthreads();

    const int bn = bh >> 3, h = bh & 7;
    const size_t col0 = (size_t)bn * T_SEQ + qt * TQ + tid;
    #pragma unroll
    for (int i = 0; i < HDIM; i++) {
        g_attT[(size_t)(h * HDIM + i) * ROWS_TOT + col0] = Os[i][tid];
    }
}

// ---------------------------------------------------------------------------
// Output projection + transpose back to [B, T, N, E]. 64 rows/block.
// ---------------------------------------------------------------------------
#define PROJ_ROWS 64
__global__ __launch_bounds__(256) void proj_kernel(
    const float* __restrict__ w,     // [E, E]
    const float* __restrict__ bias,  // [E]
    float* __restrict__ out)         // [B, T, 4, E]
{
    __shared__ __align__(16) float sxT[E_DIM][PROJ_ROWS]; // 64KB
    const int tid = threadIdx.x;
    const int r0 = blockIdx.x * PROJ_ROWS;
    const int bn = r0 / T_SEQ;
    const int t0 = r0 % T_SEQ;
    const int b  = bn >> 2;
    const int n  = bn & 3;

    // staging: 4096 float4 (256 e x 16 groups), 16 per thread; conflict-free
    #pragma unroll
    for (int i = 0; i < 16; i++) {
        const int idx = tid + i * 256;
        const int e = idx >> 4;
        const int j = idx & 15;
        const float4 v = *(const float4*)(g_attT + (size_t)e * ROWS_TOT + r0 + 4 * j);
        *(float4*)&sxT[e][4 * j] = v;
    }
    __syncthreads();

    const float bb = bias[tid];
    ull acc[32];
    #pragma unroll
    for (int p = 0; p < 32; p++) acc[p] = pack2(bb, bb);

    #pragma unroll 1
    for (int e0 = 0; e0 < E_DIM; e0 += 8) {
        float wv[8];
        #pragma unroll
        for (int j = 0; j < 8; j++) wv[j] = w[(e0 + j) * E_DIM + tid];
        #pragma unroll
        for (int j = 0; j < 8; j++) {
            const ull we2 = pack2(wv[j], wv[j]);
            const ulonglong2* xp = (const ulonglong2*)&sxT[e0 + j][0];
            #pragma unroll
            for (int q = 0; q < 16; q++) {
                const ulonglong2 xx = xp[q];
                acc[2 * q]     = fma2(xx.x, we2, acc[2 * q]);
                acc[2 * q + 1] = fma2(xx.y, we2, acc[2 * q + 1]);
            }
        }
    }

    #pragma unroll
    for (int p = 0; p < 32; p++) {
        float f0, f1;
        unpack2(acc[p], f0, f1);
        const int ta = t0 + 2 * p, tb = ta + 1;
        out[(((size_t)(b * T_SEQ + ta) * 4) + n) * E_DIM + tid] = f0;
        out[(((size_t)(b * T_SEQ + tb) * 4) + n) * E_DIM + tid] = f1;
    }
}

// ---------------------------------------------------------------------------
extern "C" void kernel_launch(void* const* d_in, const int* in_sizes, int n_in,
                              void* d_out, int out_size) {
    const float* inp    = (const float*)d_in[0];
    const float* w_attn = (const float*)d_in[1];
    const float* b_attn = (const float*)d_in[2];
    const float* w_proj = (const float*)d_in[3];
    const float* b_proj = (const float*)d_in[4];
    float* out = (float*)d_out;

    rope_table_kernel<<<T_SEQ * HALF / 256, 256>>>();
    qkv_rope_kernel<<<dim3(ROWS_TOT / QKV_ROWS, 3), 256>>>(inp, w_attn, b_attn);
    attn_kernel<<<dim3(8, BH, 2), TQ>>>();
    combine_kernel<<<dim3(8, BH), TQ>>>();
    proj_kernel<<<ROWS_TOT / PROJ_ROWS, 256>>>(w_proj, b_proj, out);
}

// round 7
// speedup vs baseline: 1.1544x; 1.1544x over previous
#include <cuda_runtime.h>
#include <cstdint>
#include <math.h>

#define T_SEQ 1024
#define E_DIM 256
#define NHEAD 8
#define HDIM 32
#define HALF 16
#define BNUM 8          // B*N = 2*4
#define BH (BNUM*NHEAD) // 64
#define ROWS_TOT (BNUM*T_SEQ)   // 8192

typedef unsigned long long ull;

// Scratch (static device arrays; no allocation allowed)
__device__ float g_q[BNUM * T_SEQ * E_DIM];     // [bh][t][d]
__device__ float g_k[BNUM * T_SEQ * E_DIM];
__device__ float g_v[BNUM * T_SEQ * E_DIM];
__device__ float g_attT[E_DIM * ROWS_TOT];      // TRANSPOSED: [e][bn*T + t]
__device__ float g_po[2 * BH * T_SEQ * HDIM];   // split-K partial o (unnormalized)
__device__ float g_pm[2 * BH * T_SEQ];          // split-K partial max (log2 domain)
__device__ float g_pl[2 * BH * T_SEQ];          // split-K partial sum
__device__ float g_cos[T_SEQ * HALF];
__device__ float g_sin[T_SEQ * HALF];

// ---------------------------------------------------------------------------
// f32x2 packed-math helpers
// ---------------------------------------------------------------------------
__device__ __forceinline__ ull pack2(float lo, float hi) {
    ull r;
    asm("mov.b64 %0, {%1, %2};" : "=l"(r) : "f"(lo), "f"(hi));
    return r;
}
__device__ __forceinline__ void unpack2(ull v, float& lo, float& hi) {
    asm("mov.b64 {%0, %1}, %2;" : "=f"(lo), "=f"(hi) : "l"(v));
}
__device__ __forceinline__ ull fma2(ull a, ull b, ull c) {
    ull d;
    asm("fma.rn.f32x2 %0, %1, %2, %3;" : "=l"(d) : "l"(a), "l"(b), "l"(c));
    return d;
}
__device__ __forceinline__ ull mul2(ull a, ull b) {
    ull d;
    asm("mul.rn.f32x2 %0, %1, %2;" : "=l"(d) : "l"(a), "l"(b));
    return d;
}

// cp.async helpers (16B)
__device__ __forceinline__ void cp_async16(uint32_t saddr, const void* gptr) {
    asm volatile("cp.async.cg.shared.global [%0], [%1], 16;" :: "r"(saddr), "l"(gptr));
}
__device__ __forceinline__ void cp_commit() {
    asm volatile("cp.async.commit_group;");
}
template <int N>
__device__ __forceinline__ void cp_wait() {
    asm volatile("cp.async.wait_group %0;" :: "n"(N));
}
__device__ __forceinline__ uint32_t smem_u32(const void* p) {
    uint32_t a;
    asm("{ .reg .u64 t; cvta.to.shared.u64 t, %1; cvt.u32.u64 %0, t; }" : "=r"(a) : "l"(p));
    return a;
}

// ---------------------------------------------------------------------------
// RoPE table. fp64 only for the 16 inv_freq pows + range reduction.
// ---------------------------------------------------------------------------
__global__ __launch_bounds__(256) void rope_table_kernel() {
    __shared__ double s_inv[HALF];
    if (threadIdx.x < HALF) {
        s_inv[threadIdx.x] = pow(10000.0, -(double)threadIdx.x / 16.0);
    }
    __syncthreads();
    int i = blockIdx.x * blockDim.x + threadIdx.x;
    int t = i >> 4;
    int f = i & 15;
    float angf = (float)t * (float)s_inv[f];       // fp32, matches reference
    double ad = (double)angf;
    double k  = rint(ad * 0.15915494309189535);
    double r  = ad - k * 6.283185307179586;
    float rf  = (float)r;
    g_cos[i] = cosf(rf);
    g_sin[i] = sinf(rf);
}

// ---------------------------------------------------------------------------
// Fused QKV GEMM + RoPE (R5 structure). 16 rows/block, 256 threads,
// 8-e w-prefetch chunks, register RoPE via shfl_xor(16).
// ---------------------------------------------------------------------------
#define QKV_ROWS 16
__global__ __launch_bounds__(256, 2) void qkv_rope_kernel(
    const float* __restrict__ inp,   // [B, T, 4, E]
    const float* __restrict__ w,     // [E, 3E]
    const float* __restrict__ bias)  // [3E]
{
    __shared__ __align__(16) float sxT[E_DIM][QKV_ROWS]; // 16KB transposed x

    const int tid = threadIdx.x;
    const int r0 = blockIdx.x * QKV_ROWS;
    const int bn = r0 / T_SEQ;
    const int t0 = r0 % T_SEQ;
    const int b  = bn >> 2;
    const int n  = bn & 3;

    #pragma unroll
    for (int rr = 0; rr < QKV_ROWS; rr++) {
        sxT[tid][rr] = inp[(((size_t)(b * T_SEQ + t0 + rr) * 4) + n) * E_DIM + tid];
    }
    __syncthreads();

    const float bq = bias[tid];
    const float bk = bias[E_DIM + tid];
    const float bv = bias[2 * E_DIM + tid];
    ull aq[8], ak[8], av[8];
    #pragma unroll
    for (int p = 0; p < 8; p++) { aq[p] = pack2(bq, bq); ak[p] = pack2(bk, bk); av[p] = pack2(bv, bv); }

    #pragma unroll 1
    for (int e0 = 0; e0 < E_DIM; e0 += 8) {
        float wq[8], wk[8], wv[8];
        #pragma unroll
        for (int j = 0; j < 8; j++) {
            const float* wp = w + (e0 + j) * 768 + tid;
            wq[j] = wp[0];
            wk[j] = wp[E_DIM];
            wv[j] = wp[2 * E_DIM];
        }
        #pragma unroll
        for (int j = 0; j < 8; j++) {
            const int e = e0 + j;
            const ull wq2 = pack2(wq[j], wq[j]);
            const ull wk2 = pack2(wk[j], wk[j]);
            const ull wv2 = pack2(wv[j], wv[j]);
            const ulonglong2* xp = (const ulonglong2*)&sxT[e][0];
            const ulonglong2 x0 = xp[0], x1 = xp[1], x2 = xp[2], x3 = xp[3];
            aq[0] = fma2(x0.x, wq2, aq[0]); aq[1] = fma2(x0.y, wq2, aq[1]);
            aq[2] = fma2(x1.x, wq2, aq[2]); aq[3] = fma2(x1.y, wq2, aq[3]);
            aq[4] = fma2(x2.x, wq2, aq[4]); aq[5] = fma2(x2.y, wq2, aq[5]);
            aq[6] = fma2(x3.x, wq2, aq[6]); aq[7] = fma2(x3.y, wq2, aq[7]);
            ak[0] = fma2(x0.x, wk2, ak[0]); ak[1] = fma2(x0.y, wk2, ak[1]);
            ak[2] = fma2(x1.x, wk2, ak[2]); ak[3] = fma2(x1.y, wk2, ak[3]);
            ak[4] = fma2(x2.x, wk2, ak[4]); ak[5] = fma2(x2.y, wk2, ak[5]);
            ak[6] = fma2(x3.x, wk2, ak[6]); ak[7] = fma2(x3.y, wk2, ak[7]);
            av[0] = fma2(x0.x, wv2, av[0]); av[1] = fma2(x0.y, wv2, av[1]);
            av[2] = fma2(x1.x, wv2, av[2]); av[3] = fma2(x1.y, wv2, av[3]);
            av[4] = fma2(x2.x, wv2, av[4]); av[5] = fma2(x2.y, wv2, av[5]);
            av[6] = fma2(x3.x, wv2, av[6]); av[7] = fma2(x3.y, wv2, av[7]);
        }
    }

    // RoPE in registers: partner lane is tid^16 (same warp, same h)
    const int h  = tid >> 5;
    const int dd = tid & 31;
    const int f  = dd & 15;
    const float sgn = (dd < HALF) ? -1.0f : 1.0f;
    const size_t rowbase = ((size_t)(bn * NHEAD + h) * T_SEQ + t0) * HDIM + dd;

    #pragma unroll
    for (int p = 0; p < 8; p++) {
        float q0, q1, k0, k1, v0, v1;
        unpack2(aq[p], q0, q1);
        unpack2(ak[p], k0, k1);
        unpack2(av[p], v0, v1);
        const float qp0 = __shfl_xor_sync(0xffffffffu, q0, 16);
        const float qp1 = __shfl_xor_sync(0xffffffffu, q1, 16);
        const float kp0 = __shfl_xor_sync(0xffffffffu, k0, 16);
        const float kp1 = __shfl_xor_sync(0xffffffffu, k1, 16);
        const int t = t0 + 2 * p;
        const float c0 = g_cos[t * HALF + f],       s0 = g_sin[t * HALF + f];
        const float c1 = g_cos[(t + 1) * HALF + f], s1 = g_sin[(t + 1) * HALF + f];
        const size_t base = rowbase + (size_t)(2 * p) * HDIM;
        g_q[base]        = q0 * c0 + sgn * qp0 * s0;
        g_k[base]        = k0 * c0 + sgn * kp0 * s0;
        g_v[base]        = v0;
        g_q[base + HDIM] = q1 * c1 + sgn * qp1 * s1;
        g_k[base + HDIM] = k1 * c1 + sgn * kp1 * s1;
        g_v[base + HDIM] = v1;
    }
}

// ---------------------------------------------------------------------------
// Flash attention stage 1 (split-K x2), cp.async double-buffered K/V tiles,
// exp2-domain softmax. Tree reductions + batched EX2 to shorten the per-tile
// critical path.
// ---------------------------------------------------------------------------
#define TQ 128
#define TK 32
#define KSPLIT 512
__global__ __launch_bounds__(TQ) void attn_kernel() {
    const int qt  = 7 - blockIdx.x;         // heavy tiles first
    const int bh  = blockIdx.y;
    const int sp  = blockIdx.z;
    const int tid = threadIdx.x;
    const int qrow = qt * TQ + tid;
    const size_t pidx = ((size_t)sp * BH + bh) * T_SEQ + qrow;

    const int kbeg = sp * KSPLIT;
    const int kend = min((sp + 1) * KSPLIT, (qt + 1) * TQ);

    if (kbeg >= kend) {                     // empty split (sp=1, qt<4)
        g_pm[pidx] = -1e30f;
        g_pl[pidx] = 0.0f;
        ull* op = (ull*)(g_po + pidx * HDIM);
        #pragma unroll
        for (int i = 0; i < 16; i++) op[i] = 0ull;
        return;
    }

    __shared__ __align__(16) float Ks[2][TK][HDIM];
    __shared__ __align__(16) float Vs[2][TK][HDIM];

    const float scale = 0.17677669529663687f * 1.4426950408889634f; // /sqrt(32)*log2(e)
    const ull scale2 = pack2(scale, scale);

    ull qd[16];
    {
        const ull* qp = (const ull*)(g_q + ((size_t)bh * T_SEQ + qrow) * HDIM);
        #pragma unroll
        for (int i = 0; i < 16; i++) qd[i] = mul2(qp[i], scale2);
    }

    ull od[16];
    #pragma unroll
    for (int i = 0; i < 16; i++) od[i] = 0ull;
    float m = -1e30f, l = 0.0f;

    const int ntiles = (kend - kbeg) / TK;

    {
        const float* ksrc = g_k + ((size_t)bh * T_SEQ + kbeg) * HDIM;
        const float* vsrc = g_v + ((size_t)bh * T_SEQ + kbeg) * HDIM;
        const uint32_t kdst = smem_u32(&Ks[0][0][0]);
        const uint32_t vdst = smem_u32(&Vs[0][0][0]);
        #pragma unroll
        for (int i = 0; i < 2; i++) {
            const int off = (tid + i * TQ) * 4;
            cp_async16(kdst + off * 4, ksrc + off);
            cp_async16(vdst + off * 4, vsrc + off);
        }
        cp_commit();
    }

    for (int kt = 0; kt < ntiles; kt++) {
        const int k0 = kbeg + kt * TK;
        if (kt + 1 < ntiles) {
            const int nb = (kt + 1) & 1;
            const float* ksrc = g_k + ((size_t)bh * T_SEQ + k0 + TK) * HDIM;
            const float* vsrc = g_v + ((size_t)bh * T_SEQ + k0 + TK) * HDIM;
            const uint32_t kdst = smem_u32(&Ks[nb][0][0]);
            const uint32_t vdst = smem_u32(&Vs[nb][0][0]);
            #pragma unroll
            for (int i = 0; i < 2; i++) {
                const int off = (tid + i * TQ) * 4;
                cp_async16(kdst + off * 4, ksrc + off);
                cp_async16(vdst + off * 4, vsrc + off);
            }
            cp_commit();
            cp_wait<1>();
        } else {
            cp_wait<0>();
        }
        __syncthreads();
        const int cb = kt & 1;

        float s[TK];
        #pragma unroll
        for (int j = 0; j < TK; j++) {
            ull acc = 0ull;
            const ulonglong2* kp = (const ulonglong2*)&Ks[cb][j][0];
            #pragma unroll
            for (int i = 0; i < 8; i++) {
                const ulonglong2 kk = kp[i];
                acc = fma2(qd[2 * i], kk.x, acc);
                acc = fma2(qd[2 * i + 1], kk.y, acc);
            }
            float lo, hi;
            unpack2(acc, lo, hi);
            s[j] = (k0 + j <= qrow) ? (lo + hi) : -1e30f;
        }

        // tree max over the tile (depth 5 instead of 32)
        float mx[16];
        #pragma unroll
        for (int j = 0; j < 16; j++) mx[j] = fmaxf(s[j], s[j + 16]);
        #pragma unroll
        for (int j = 0; j < 8; j++) mx[j] = fmaxf(mx[j], mx[j + 8]);
        #pragma unroll
        for (int j = 0; j < 4; j++) mx[j] = fmaxf(mx[j], mx[j + 4]);
        const float mt = fmaxf(fmaxf(fmaxf(mx[0], mx[1]), fmaxf(mx[2], mx[3])), m);

        const float alpha = exp2f(m - mt);
        m = mt;

        // batch all 32 EX2s (independent, MLP across the MUFU pipe)
        #pragma unroll
        for (int j = 0; j < TK; j++) s[j] = exp2f(s[j] - mt);

        // tree sum for l
        float sm[16];
        #pragma unroll
        for (int j = 0; j < 16; j++) sm[j] = s[j] + s[j + 16];
        #pragma unroll
        for (int j = 0; j < 8; j++) sm[j] += sm[j + 8];
        #pragma unroll
        for (int j = 0; j < 4; j++) sm[j] += sm[j + 4];
        l = l * alpha + ((sm[0] + sm[1]) + (sm[2] + sm[3]));

        const ull alpha2 = pack2(alpha, alpha);
        #pragma unroll
        for (int i = 0; i < 16; i++) od[i] = mul2(od[i], alpha2);

        // PV sweep: pure FMA, p already in registers
        #pragma unroll
        for (int j = 0; j < TK; j++) {
            const ull p2 = pack2(s[j], s[j]);
            const ulonglong2* vp = (const ulonglong2*)&Vs[cb][j][0];
            #pragma unroll
            for (int i = 0; i < 8; i++) {
                const ulonglong2 vvv = vp[i];
                od[2 * i]     = fma2(p2, vvv.x, od[2 * i]);
                od[2 * i + 1] = fma2(p2, vvv.y, od[2 * i + 1]);
            }
        }
        __syncthreads();
    }

    g_pm[pidx] = m;
    g_pl[pidx] = l;
    ull* op = (ull*)(g_po + pidx * HDIM);
    #pragma unroll
    for (int i = 0; i < 16; i++) op[i] = od[i];
}

// ---------------------------------------------------------------------------
// Stage 2: merge split-K partials; write TRANSPOSED g_attT[e][row].
// ---------------------------------------------------------------------------
__global__ __launch_bounds__(TQ) void combine_kernel() {
    __shared__ float Os[HDIM][TQ + 1];
    __shared__ float sw0[TQ], sw1[TQ], sinv[TQ];

    const int qt  = blockIdx.x;
    const int bh  = blockIdx.y;
    const int tid = threadIdx.x;
    const int qrow = qt * TQ + tid;
    const size_t p0 = ((size_t)bh) * T_SEQ + qrow;
    const size_t p1 = ((size_t)BH + bh) * T_SEQ + qrow;

    const float m0 = g_pm[p0], m1 = g_pm[p1];
    const float l0 = g_pl[p0], l1 = g_pl[p1];
    const float M  = fmaxf(m0, m1);
    const float w0 = exp2f(m0 - M);
    const float w1 = exp2f(m1 - M);
    sw0[tid]  = w0;
    sw1[tid]  = w1;
    sinv[tid] = 1.0f / (w0 * l0 + w1 * l1);
    __syncthreads();

    const float* o0 = g_po + (((size_t)bh) * T_SEQ + qt * TQ) * HDIM;
    const float* o1 = g_po + (((size_t)BH + bh) * T_SEQ + qt * TQ) * HDIM;
    #pragma unroll
    for (int i = 0; i < 32; i++) {
        const int idx = i * TQ + tid;
        const int d = idx & 31;
        const int r = idx >> 5;
        Os[d][r] = (sw0[r] * o0[idx] + sw1[r] * o1[idx]) * sinv[r];
    }
    __syncthreads();

    const int bn = bh >> 3, h = bh & 7;
    const size_t col0 = (size_t)bn * T_SEQ + qt * TQ + tid;
    #pragma unroll
    for (int i = 0; i < HDIM; i++) {
        g_attT[(size_t)(h * HDIM + i) * ROWS_TOT + col0] = Os[i][tid];
    }
}

// ---------------------------------------------------------------------------
// Output projection + transpose back to [B, T, N, E]. 32 rows/block.
// Each thread: 2 adjacent cols x 16 rows (halves LDS per FMA, w via LDG.64).
// ---------------------------------------------------------------------------
#define PROJ_ROWS 32
__global__ __launch_bounds__(256, 2) void proj_kernel(
    const float* __restrict__ w,     // [E, E]
    const float* __restrict__ bias,  // [E]
    float* __restrict__ out)         // [B, T, 4, E]
{
    __shared__ __align__(16) float sxT[E_DIM][PROJ_ROWS]; // 32KB
    const int tid = threadIdx.x;
    const int r0 = blockIdx.x * PROJ_ROWS;
    const int bn = r0 / T_SEQ;
    const int t0 = r0 % T_SEQ;
    const int b  = bn >> 2;
    const int n  = bn & 3;

    // staging: 2048 float4, 8 per thread; LDG coalesced, STS conflict-free
    #pragma unroll
    for (int i = 0; i < 8; i++) {
        const int idx = tid + i * 256;
        const int e = idx >> 3;
        const int j = idx & 7;
        const float4 v = *(const float4*)(g_attT + (size_t)e * ROWS_TOT + r0 + 4 * j);
        *(float4*)&sxT[e][4 * j] = v;
    }
    __syncthreads();

    // thread -> (col pair, row half)
    const int cp   = tid & 127;          // 0..127 -> cols 2cp, 2cp+1
    const int rh   = tid >> 7;           // 0..1   -> rows rh*16 .. rh*16+15
    const int c0   = 2 * cp;
    const int rb   = rh * 16;

    const float2 bb = *(const float2*)(bias + c0);
    ull accA[8], accB[8];                // accA: col c0, accB: col c0+1 (rows packed)
    #pragma unroll
    for (int p = 0; p < 8; p++) { accA[p] = pack2(bb.x, bb.x); accB[p] = pack2(bb.y, bb.y); }

    #pragma unroll 1
    for (int e0 = 0; e0 < E_DIM; e0 += 8) {
        float2 wv[8];
        #pragma unroll
        for (int j = 0; j < 8; j++) wv[j] = *(const float2*)(w + (e0 + j) * E_DIM + c0);
        #pragma unroll
        for (int j = 0; j < 8; j++) {
            const ull wA = pack2(wv[j].x, wv[j].x);
            const ull wB = pack2(wv[j].y, wv[j].y);
            const ulonglong2* xp = (const ulonglong2*)&sxT[e0 + j][rb];
            const ulonglong2 x0 = xp[0], x1 = xp[1], x2 = xp[2], x3 = xp[3];
            accA[0] = fma2(x0.x, wA, accA[0]); accA[1] = fma2(x0.y, wA, accA[1]);
            accA[2] = fma2(x1.x, wA, accA[2]); accA[3] = fma2(x1.y, wA, accA[3]);
            accA[4] = fma2(x2.x, wA, accA[4]); accA[5] = fma2(x2.y, wA, accA[5]);
            accA[6] = fma2(x3.x, wA, accA[6]); accA[7] = fma2(x3.y, wA, accA[7]);
            accB[0] = fma2(x0.x, wB, accB[0]); accB[1] = fma2(x0.y, wB, accB[1]);
            accB[2] = fma2(x1.x, wB, accB[2]); accB[3] = fma2(x1.y, wB, accB[3]);
            accB[4] = fma2(x2.x, wB, accB[4]); accB[5] = fma2(x2.y, wB, accB[5]);
            accB[6] = fma2(x3.x, wB, accB[6]); accB[7] = fma2(x3.y, wB, accB[7]);
        }
    }

    #pragma unroll
    for (int p = 0; p < 8; p++) {
        float a0, a1, b0, b1;
        unpack2(accA[p], a0, a1);
        unpack2(accB[p], b0, b1);
        const int ta = t0 + rb + 2 * p, tb = ta + 1;
        float2* oa = (float2*)(out + (((size_t)(b * T_SEQ + ta) * 4) + n) * E_DIM + c0);
        float2* ob = (float2*)(out + (((size_t)(b * T_SEQ + tb) * 4) + n) * E_DIM + c0);
        *oa = make_float2(a0, b0);
        *ob = make_float2(a1, b1);
    }
}

// ---------------------------------------------------------------------------
extern "C" void kernel_launch(void* const* d_in, const int* in_sizes, int n_in,
                              void* d_out, int out_size) {
    const float* inp    = (const float*)d_in[0];
    const float* w_attn = (const float*)d_in[1];
    const float* b_attn = (const float*)d_in[2];
    const float* w_proj = (const float*)d_in[3];
    const float* b_proj = (const float*)d_in[4];
    float* out = (float*)d_out;

    rope_table_kernel<<<T_SEQ * HALF / 256, 256>>>();
    qkv_rope_kernel<<<ROWS_TOT / QKV_ROWS, 256>>>(inp, w_attn, b_attn);
    attn_kernel<<<dim3(8, BH, 2), TQ>>>();
    combine_kernel<<<dim3(8, BH), TQ>>>();
    proj_kernel<<<ROWS_TOT / PROJ_ROWS, 256>>>(w_proj, b_proj, out);
}

// round 8
// speedup vs baseline: 1.1911x; 1.0318x over previous
#include <cuda_runtime.h>
#include <cstdint>
#include <math.h>

#define T_SEQ 1024
#define E_DIM 256
#define NHEAD 8
#define HDIM 32
#define HALF 16
#define BNUM 8          // B*N = 2*4
#define BH (BNUM*NHEAD) // 64
#define ROWS_TOT (BNUM*T_SEQ)   // 8192

typedef unsigned long long ull;

// Scratch (static device arrays; no allocation allowed)
__device__ float g_q[BNUM * T_SEQ * E_DIM];     // [bh][t][d]
__device__ float g_k[BNUM * T_SEQ * E_DIM];
__device__ float g_v[BNUM * T_SEQ * E_DIM];
__device__ float g_po[2 * BH * T_SEQ * HDIM];   // split-K partial o (unnormalized)
__device__ float g_pm[2 * BH * T_SEQ];          // split-K partial max (log2 domain)
__device__ float g_pl[2 * BH * T_SEQ];          // split-K partial sum
__device__ float g_cos[T_SEQ * HALF];
__device__ float g_sin[T_SEQ * HALF];

// ---------------------------------------------------------------------------
// f32x2 packed-math helpers
// ---------------------------------------------------------------------------
__device__ __forceinline__ ull pack2(float lo, float hi) {
    ull r;
    asm("mov.b64 %0, {%1, %2};" : "=l"(r) : "f"(lo), "f"(hi));
    return r;
}
__device__ __forceinline__ void unpack2(ull v, float& lo, float& hi) {
    asm("mov.b64 {%0, %1}, %2;" : "=f"(lo), "=f"(hi) : "l"(v));
}
__device__ __forceinline__ ull fma2(ull a, ull b, ull c) {
    ull d;
    asm("fma.rn.f32x2 %0, %1, %2, %3;" : "=l"(d) : "l"(a), "l"(b), "l"(c));
    return d;
}
__device__ __forceinline__ ull mul2(ull a, ull b) {
    ull d;
    asm("mul.rn.f32x2 %0, %1, %2;" : "=l"(d) : "l"(a), "l"(b));
    return d;
}

// cp.async helpers (16B)
__device__ __forceinline__ void cp_async16(uint32_t saddr, const void* gptr) {
    asm volatile("cp.async.cg.shared.global [%0], [%1], 16;" :: "r"(saddr), "l"(gptr));
}
__device__ __forceinline__ void cp_commit() {
    asm volatile("cp.async.commit_group;");
}
template <int N>
__device__ __forceinline__ void cp_wait() {
    asm volatile("cp.async.wait_group %0;" :: "n"(N));
}
__device__ __forceinline__ uint32_t smem_u32(const void* p) {
    uint32_t a;
    asm("{ .reg .u64 t; cvta.to.shared.u64 t, %1; cvt.u32.u64 %0, t; }" : "=r"(a) : "l"(p));
    return a;
}

// ---------------------------------------------------------------------------
// RoPE table. fp64 only for the 16 inv_freq pows + range reduction.
// ---------------------------------------------------------------------------
__global__ __launch_bounds__(256) void rope_table_kernel() {
    __shared__ double s_inv[HALF];
    if (threadIdx.x < HALF) {
        s_inv[threadIdx.x] = pow(10000.0, -(double)threadIdx.x / 16.0);
    }
    __syncthreads();
    int i = blockIdx.x * blockDim.x + threadIdx.x;
    int t = i >> 4;
    int f = i & 15;
    float angf = (float)t * (float)s_inv[f];       // fp32, matches reference
    double ad = (double)angf;
    double k  = rint(ad * 0.15915494309189535);
    double r  = ad - k * 6.283185307179586;
    float rf  = (float)r;
    g_cos[i] = cosf(rf);
    g_sin[i] = sinf(rf);
}

// ---------------------------------------------------------------------------
// Fused QKV GEMM + RoPE. 16 rows/block, 256 threads, 8-e w-prefetch chunks,
// register RoPE via shfl_xor(16). No occupancy hint (avoid forced spills).
// ---------------------------------------------------------------------------
#define QKV_ROWS 16
__global__ __launch_bounds__(256) void qkv_rope_kernel(
    const float* __restrict__ inp,   // [B, T, 4, E]
    const float* __restrict__ w,     // [E, 3E]
    const float* __restrict__ bias)  // [3E]
{
    __shared__ __align__(16) float sxT[E_DIM][QKV_ROWS]; // 16KB transposed x

    const int tid = threadIdx.x;
    const int r0 = blockIdx.x * QKV_ROWS;
    const int bn = r0 / T_SEQ;
    const int t0 = r0 % T_SEQ;
    const int b  = bn >> 2;
    const int n  = bn & 3;

    #pragma unroll
    for (int rr = 0; rr < QKV_ROWS; rr++) {
        sxT[tid][rr] = inp[(((size_t)(b * T_SEQ + t0 + rr) * 4) + n) * E_DIM + tid];
    }
    __syncthreads();

    const float bq = bias[tid];
    const float bk = bias[E_DIM + tid];
    const float bv = bias[2 * E_DIM + tid];
    ull aq[8], ak[8], av[8];
    #pragma unroll
    for (int p = 0; p < 8; p++) { aq[p] = pack2(bq, bq); ak[p] = pack2(bk, bk); av[p] = pack2(bv, bv); }

    #pragma unroll 1
    for (int e0 = 0; e0 < E_DIM; e0 += 8) {
        float wq[8], wk[8], wv[8];
        #pragma unroll
        for (int j = 0; j < 8; j++) {
            const float* wp = w + (e0 + j) * 768 + tid;
            wq[j] = wp[0];
            wk[j] = wp[E_DIM];
            wv[j] = wp[2 * E_DIM];
        }
        #pragma unroll
        for (int j = 0; j < 8; j++) {
            const int e = e0 + j;
            const ull wq2 = pack2(wq[j], wq[j]);
            const ull wk2 = pack2(wk[j], wk[j]);
            const ull wv2 = pack2(wv[j], wv[j]);
            const ulonglong2* xp = (const ulonglong2*)&sxT[e][0];
            const ulonglong2 x0 = xp[0], x1 = xp[1], x2 = xp[2], x3 = xp[3];
            aq[0] = fma2(x0.x, wq2, aq[0]); aq[1] = fma2(x0.y, wq2, aq[1]);
            aq[2] = fma2(x1.x, wq2, aq[2]); aq[3] = fma2(x1.y, wq2, aq[3]);
            aq[4] = fma2(x2.x, wq2, aq[4]); aq[5] = fma2(x2.y, wq2, aq[5]);
            aq[6] = fma2(x3.x, wq2, aq[6]); aq[7] = fma2(x3.y, wq2, aq[7]);
            ak[0] = fma2(x0.x, wk2, ak[0]); ak[1] = fma2(x0.y, wk2, ak[1]);
            ak[2] = fma2(x1.x, wk2, ak[2]); ak[3] = fma2(x1.y, wk2, ak[3]);
            ak[4] = fma2(x2.x, wk2, ak[4]); ak[5] = fma2(x2.y, wk2, ak[5]);
            ak[6] = fma2(x3.x, wk2, ak[6]); ak[7] = fma2(x3.y, wk2, ak[7]);
            av[0] = fma2(x0.x, wv2, av[0]); av[1] = fma2(x0.y, wv2, av[1]);
            av[2] = fma2(x1.x, wv2, av[2]); av[3] = fma2(x1.y, wv2, av[3]);
            av[4] = fma2(x2.x, wv2, av[4]); av[5] = fma2(x2.y, wv2, av[5]);
            av[6] = fma2(x3.x, wv2, av[6]); av[7] = fma2(x3.y, wv2, av[7]);
        }
    }

    // RoPE in registers: partner lane is tid^16 (same warp, same h)
    const int h  = tid >> 5;
    const int dd = tid & 31;
    const int f  = dd & 15;
    const float sgn = (dd < HALF) ? -1.0f : 1.0f;
    const size_t rowbase = ((size_t)(bn * NHEAD + h) * T_SEQ + t0) * HDIM + dd;

    #pragma unroll
    for (int p = 0; p < 8; p++) {
        float q0, q1, k0, k1, v0, v1;
        unpack2(aq[p], q0, q1);
        unpack2(ak[p], k0, k1);
        unpack2(av[p], v0, v1);
        const float qp0 = __shfl_xor_sync(0xffffffffu, q0, 16);
        const float qp1 = __shfl_xor_sync(0xffffffffu, q1, 16);
        const float kp0 = __shfl_xor_sync(0xffffffffu, k0, 16);
        const float kp1 = __shfl_xor_sync(0xffffffffu, k1, 16);
        const int t = t0 + 2 * p;
        const float c0 = g_cos[t * HALF + f],       s0 = g_sin[t * HALF + f];
        const float c1 = g_cos[(t + 1) * HALF + f], s1 = g_sin[(t + 1) * HALF + f];
        const size_t base = rowbase + (size_t)(2 * p) * HDIM;
        g_q[base]        = q0 * c0 + sgn * qp0 * s0;
        g_k[base]        = k0 * c0 + sgn * kp0 * s0;
        g_v[base]        = v0;
        g_q[base + HDIM] = q1 * c1 + sgn * qp1 * s1;
        g_k[base + HDIM] = k1 * c1 + sgn * kp1 * s1;
        g_v[base + HDIM] = v1;
    }
}

// ---------------------------------------------------------------------------
// Flash attention stage 1 (split-K x2), cp.async double-buffered K/V tiles,
// exp2-domain softmax, full-tile specialization (no causal select on tiles
// fully below the q-tile).
// ---------------------------------------------------------------------------
#define TQ 128
#define TK 32
#define KSPLIT 512
__global__ __launch_bounds__(TQ) void attn_kernel() {
    const int qt  = 7 - blockIdx.x;         // heavy tiles first
    const int bh  = blockIdx.y;
    const int sp  = blockIdx.z;
    const int tid = threadIdx.x;
    const int qrow = qt * TQ + tid;
    const size_t pidx = ((size_t)sp * BH + bh) * T_SEQ + qrow;

    const int kbeg = sp * KSPLIT;
    const int kend = min((sp + 1) * KSPLIT, (qt + 1) * TQ);

    if (kbeg >= kend) {                     // empty split (sp=1, qt<4)
        g_pm[pidx] = -1e30f;
        g_pl[pidx] = 0.0f;
        ull* op = (ull*)(g_po + pidx * HDIM);
        #pragma unroll
        for (int i = 0; i < 16; i++) op[i] = 0ull;
        return;
    }

    __shared__ __align__(16) float Ks[2][TK][HDIM];
    __shared__ __align__(16) float Vs[2][TK][HDIM];

    const float scale = 0.17677669529663687f * 1.4426950408889634f; // /sqrt(32)*log2(e)
    const ull scale2 = pack2(scale, scale);

    ull qd[16];
    {
        const ull* qp = (const ull*)(g_q + ((size_t)bh * T_SEQ + qrow) * HDIM);
        #pragma unroll
        for (int i = 0; i < 16; i++) qd[i] = mul2(qp[i], scale2);
    }

    ull od[16];
    #pragma unroll
    for (int i = 0; i < 16; i++) od[i] = 0ull;
    float m = -1e30f, l = 0.0f;

    const int ntiles = (kend - kbeg) / TK;

    {
        const float* ksrc = g_k + ((size_t)bh * T_SEQ + kbeg) * HDIM;
        const float* vsrc = g_v + ((size_t)bh * T_SEQ + kbeg) * HDIM;
        const uint32_t kdst = smem_u32(&Ks[0][0][0]);
        const uint32_t vdst = smem_u32(&Vs[0][0][0]);
        #pragma unroll
        for (int i = 0; i < 2; i++) {
            const int off = (tid + i * TQ) * 4;
            cp_async16(kdst + off * 4, ksrc + off);
            cp_async16(vdst + off * 4, vsrc + off);
        }
        cp_commit();
    }

    for (int kt = 0; kt < ntiles; kt++) {
        const int k0 = kbeg + kt * TK;
        if (kt + 1 < ntiles) {
            const int nb = (kt + 1) & 1;
            const float* ksrc = g_k + ((size_t)bh * T_SEQ + k0 + TK) * HDIM;
            const float* vsrc = g_v + ((size_t)bh * T_SEQ + k0 + TK) * HDIM;
            const uint32_t kdst = smem_u32(&Ks[nb][0][0]);
            const uint32_t vdst = smem_u32(&Vs[nb][0][0]);
            #pragma unroll
            for (int i = 0; i < 2; i++) {
                const int off = (tid + i * TQ) * 4;
                cp_async16(kdst + off * 4, ksrc + off);
                cp_async16(vdst + off * 4, vsrc + off);
            }
            cp_commit();
            cp_wait<1>();
        } else {
            cp_wait<0>();
        }
        __syncthreads();
        const int cb = kt & 1;
        const bool full = (k0 + TK <= qt * TQ);   // uniform across block

        float s[TK];
        if (full) {
            #pragma unroll
            for (int j = 0; j < TK; j++) {
                ull acc = 0ull;
                const ulonglong2* kp = (const ulonglong2*)&Ks[cb][j][0];
                #pragma unroll
                for (int i = 0; i < 8; i++) {
                    const ulonglong2 kk = kp[i];
                    acc = fma2(qd[2 * i], kk.x, acc);
                    acc = fma2(qd[2 * i + 1], kk.y, acc);
                }
                float lo, hi;
                unpack2(acc, lo, hi);
                s[j] = lo + hi;
            }
        } else {
            #pragma unroll
            for (int j = 0; j < TK; j++) {
                ull acc = 0ull;
                const ulonglong2* kp = (const ulonglong2*)&Ks[cb][j][0];
                #pragma unroll
                for (int i = 0; i < 8; i++) {
                    const ulonglong2 kk = kp[i];
                    acc = fma2(qd[2 * i], kk.x, acc);
                    acc = fma2(qd[2 * i + 1], kk.y, acc);
                }
                float lo, hi;
                unpack2(acc, lo, hi);
                s[j] = (k0 + j <= qrow) ? (lo + hi) : -1e30f;
            }
        }

        // tree max over the tile
        float mx[16];
        #pragma unroll
        for (int j = 0; j < 16; j++) mx[j] = fmaxf(s[j], s[j + 16]);
        #pragma unroll
        for (int j = 0; j < 8; j++) mx[j] = fmaxf(mx[j], mx[j + 8]);
        #pragma unroll
        for (int j = 0; j < 4; j++) mx[j] = fmaxf(mx[j], mx[j + 4]);
        const float mt = fmaxf(fmaxf(fmaxf(mx[0], mx[1]), fmaxf(mx[2], mx[3])), m);

        const float alpha = exp2f(m - mt);
        m = mt;

        // batch all 32 EX2s
        #pragma unroll
        for (int j = 0; j < TK; j++) s[j] = exp2f(s[j] - mt);

        // tree sum for l
        float sm[16];
        #pragma unroll
        for (int j = 0; j < 16; j++) sm[j] = s[j] + s[j + 16];
        #pragma unroll
        for (int j = 0; j < 8; j++) sm[j] += sm[j + 8];
        #pragma unroll
        for (int j = 0; j < 4; j++) sm[j] += sm[j + 4];
        l = l * alpha + ((sm[0] + sm[1]) + (sm[2] + sm[3]));

        const ull alpha2 = pack2(alpha, alpha);
        #pragma unroll
        for (int i = 0; i < 16; i++) od[i] = mul2(od[i], alpha2);

        // PV sweep
        #pragma unroll
        for (int j = 0; j < TK; j++) {
            const ull p2 = pack2(s[j], s[j]);
            const ulonglong2* vp = (const ulonglong2*)&Vs[cb][j][0];
            #pragma unroll
            for (int i = 0; i < 8; i++) {
                const ulonglong2 vvv = vp[i];
                od[2 * i]     = fma2(p2, vvv.x, od[2 * i]);
                od[2 * i + 1] = fma2(p2, vvv.y, od[2 * i + 1]);
            }
        }
        __syncthreads();
    }

    g_pm[pidx] = m;
    g_pl[pidx] = l;
    ull* op = (ull*)(g_po + pidx * HDIM);
    #pragma unroll
    for (int i = 0; i < 16; i++) op[i] = od[i];
}

// ---------------------------------------------------------------------------
// Fused split-K combine + output projection + transpose to [B, T, N, E].
// 32 rows/block. Combine phase: thread = (head, row), merges both partials
// directly into the staging tile (bank-conflict-free: bank == row == lane).
// GEMM phase: thread = 2 adjacent cols x 16 rows.
// ---------------------------------------------------------------------------
#define PROJ_ROWS 32
__global__ __launch_bounds__(256) void proj_kernel(
    const float* __restrict__ w,     // [E, E]
    const float* __restrict__ bias,  // [E]
    float* __restrict__ out)         // [B, T, 4, E]
{
    __shared__ __align__(16) float sxT[E_DIM][PROJ_ROWS]; // 32KB
    const int tid = threadIdx.x;
    const int r0 = blockIdx.x * PROJ_ROWS;
    const int bn = r0 / T_SEQ;
    const int t0 = r0 % T_SEQ;
    const int b  = bn >> 2;
    const int n  = bn & 3;

    // --- combine phase: 256 threads = 8 heads x 32 rows ---
    {
        const int h = tid >> 5;
        const int r = tid & 31;
        const int bh = bn * NHEAD + h;
        const size_t p0 = (size_t)bh * T_SEQ + (t0 + r);
        const size_t p1 = (size_t)(BH + bh) * T_SEQ + (t0 + r);

        const float m0 = g_pm[p0], m1 = g_pm[p1];
        const float l0 = g_pl[p0], l1 = g_pl[p1];
        const float M  = fmaxf(m0, m1);
        float w0 = exp2f(m0 - M);
        float w1 = exp2f(m1 - M);
        const float inv = 1.0f / (w0 * l0 + w1 * l1);
        w0 *= inv;
        w1 *= inv;

        const float4* o0 = (const float4*)(g_po + p0 * HDIM);
        const float4* o1 = (const float4*)(g_po + p1 * HDIM);
        #pragma unroll
        for (int i = 0; i < 8; i++) {
            const float4 a = o0[i];
            const float4 c = o1[i];
            const int e = h * HDIM + 4 * i;
            sxT[e + 0][r] = w0 * a.x + w1 * c.x;
            sxT[e + 1][r] = w0 * a.y + w1 * c.y;
            sxT[e + 2][r] = w0 * a.z + w1 * c.z;
            sxT[e + 3][r] = w0 * a.w + w1 * c.w;
        }
    }
    __syncthreads();

    // --- GEMM phase: thread -> (col pair, row half) ---
    const int cp = tid & 127;
    const int rh = tid >> 7;
    const int c0 = 2 * cp;
    const int rb = rh * 16;

    const float2 bb = *(const float2*)(bias + c0);
    ull accA[8], accB[8];
    #pragma unroll
    for (int p = 0; p < 8; p++) { accA[p] = pack2(bb.x, bb.x); accB[p] = pack2(bb.y, bb.y); }

    #pragma unroll 1
    for (int e0 = 0; e0 < E_DIM; e0 += 8) {
        float2 wv[8];
        #pragma unroll
        for (int j = 0; j < 8; j++) wv[j] = *(const float2*)(w + (e0 + j) * E_DIM + c0);
        #pragma unroll
        for (int j = 0; j < 8; j++) {
            const ull wA = pack2(wv[j].x, wv[j].x);
            const ull wB = pack2(wv[j].y, wv[j].y);
            const ulonglong2* xp = (const ulonglong2*)&sxT[e0 + j][rb];
            const ulonglong2 x0 = xp[0], x1 = xp[1], x2 = xp[2], x3 = xp[3];
            accA[0] = fma2(x0.x, wA, accA[0]); accA[1] = fma2(x0.y, wA, accA[1]);
            accA[2] = fma2(x1.x, wA, accA[2]); accA[3] = fma2(x1.y, wA, accA[3]);
            accA[4] = fma2(x2.x, wA, accA[4]); accA[5] = fma2(x2.y, wA, accA[5]);
            accA[6] = fma2(x3.x, wA, accA[6]); accA[7] = fma2(x3.y, wA, accA[7]);
            accB[0] = fma2(x0.x, wB, accB[0]); accB[1] = fma2(x0.y, wB, accB[1]);
            accB[2] = fma2(x1.x, wB, accB[2]); accB[3] = fma2(x1.y, wB, accB[3]);
            accB[4] = fma2(x2.x, wB, accB[4]); accB[5] = fma2(x2.y, wB, accB[5]);
            accB[6] = fma2(x3.x, wB, accB[6]); accB[7] = fma2(x3.y, wB, accB[7]);
        }
    }

    #pragma unroll
    for (int p = 0; p < 8; p++) {
        float a0, a1, b0, b1;
        unpack2(accA[p], a0, a1);
        unpack2(accB[p], b0, b1);
        const int ta = t0 + rb + 2 * p, tb = ta + 1;
        float2* oa = (float2*)(out + (((size_t)(b * T_SEQ + ta) * 4) + n) * E_DIM + c0);
        float2* ob = (float2*)(out + (((size_t)(b * T_SEQ + tb) * 4) + n) * E_DIM + c0);
        *oa = make_float2(a0, b0);
        *ob = make_float2(a1, b1);
    }
}

// ---------------------------------------------------------------------------
extern "C" void kernel_launch(void* const* d_in, const int* in_sizes, int n_in,
                              void* d_out, int out_size) {
    const float* inp    = (const float*)d_in[0];
    const float* w_attn = (const float*)d_in[1];
    const float* b_attn = (const float*)d_in[2];
    const float* w_proj = (const float*)d_in[3];
    const float* b_proj = (const float*)d_in[4];
    float* out = (float*)d_out;

    rope_table_kernel<<<T_SEQ * HALF / 256, 256>>>();
    qkv_rope_kernel<<<ROWS_TOT / QKV_ROWS, 256>>>(inp, w_attn, b_attn);
    attn_kernel<<<dim3(8, BH, 2), TQ>>>();
    proj_kernel<<<ROWS_TOT / PROJ_ROWS, 256>>>(w_proj, b_proj, out);
}